// round 9
// baseline (speedup 1.0000x reference)
#include <cuda_runtime.h>
#include <stdint.h>

typedef unsigned long long ull;

// ---------- static device scratch ----------
__device__ __align__(128) float g_style[16 * 512];
__device__ __align__(128) float g_dcoef[16 * 512];
__device__ __align__(128) float g_wsqT[512 * 512];
__device__ __align__(128) float g_wt[512 * 9 * 512];                 // [(ci*9+k)][co]
__device__ __align__(128) float g_xs[16 * 512 * 1024];               // x * style
__device__ __align__(128) float g_y1[(size_t)16 * 65 * 65 * 512];    // [b][u][v][co]

__device__ __forceinline__ ull pk2(float v) {
    ull r; asm("mov.b64 %0,{%1,%2};" : "=l"(r) : "f"(v), "f"(v)); return r;
}
__device__ __forceinline__ void fma2(ull& d, ull a, ull b) {
    asm("fma.rn.f32x2 %0,%1,%2,%0;" : "+l"(d) : "l"(a), "l"(b));
}
__device__ __forceinline__ float2 up2(ull v) {
    float2 r; asm("mov.b64 {%0,%1},%2;" : "=f"(r.x), "=f"(r.y) : "l"(v)); return r;
}

// ---------- K1: style[b][ci] ----------
__global__ void k_style(const float* __restrict__ wl, const float* __restrict__ aw,
                        const float* __restrict__ ab) {
    __shared__ float s[512];
    int b = blockIdx.y, ci = blockIdx.x * 256 + threadIdx.x;
    for (int i = threadIdx.x; i < 512; i += 256) s[i] = wl[b * 512 + i];
    __syncthreads();
    const float* a = aw + (size_t)ci * 512;
    float acc = 0.f;
#pragma unroll 8
    for (int d = 0; d < 512; d++) acc += s[d] * a[d];
    g_style[b * 512 + ci] = acc * 0.04419417382415922f + ab[ci];
}

// ---------- K2: weight transpose + sum of squares ----------
__global__ void k_prep(const float* __restrict__ cw) {
    int ci = blockIdx.x, co = threadIdx.x;
    const float* p = cw + ((size_t)co * 512 + ci) * 9;
    float s = 0.f;
#pragma unroll
    for (int k = 0; k < 9; k++) {
        float v = p[k];
        g_wt[(size_t)(ci * 9 + k) * 512 + co] = v;
        s += v * v;
    }
    g_wsqT[ci * 512 + co] = s;
}

// ---------- K3: xs = x * style ----------
__global__ void k_modx(const float* __restrict__ x) {
    int i = blockIdx.x * 256 + threadIdx.x;   // float4 index
    float4 v = ((const float4*)x)[i];
    float s = g_style[i >> 8];
    v.x *= s; v.y *= s; v.z *= s; v.w *= s;
    ((float4*)g_xs)[i] = v;
}

// ---------- K4: dcoef ----------
__global__ void k_dcoef() {
    __shared__ float s2[512];
    int b = blockIdx.y, co = blockIdx.x * 256 + threadIdx.x;
    for (int i = threadIdx.x; i < 512; i += 256) {
        float v = g_style[b * 512 + i];
        s2[i] = v * v;
    }
    __syncthreads();
    float a = 0.f;
#pragma unroll 4
    for (int ci = 0; ci < 512; ci++) a += g_wsqT[ci * 512 + co] * s2[ci];
    g_dcoef[b * 512 + co] = rsqrtf(a + 1e-8f);
}

// ---------- K5: gather-form transposed conv -> y1[b][u][v][co] ----------
// Tile: 16u x 16v x 64co per block. Thread: tco=t&15 (4 co), rq=(t>>4)&7, pu=t>>7.
// u = u0 + 2*rq + pu (parity warp-uniform). Gather taps per (u,v) parity.
__global__ void __launch_bounds__(256, 1) k_conv() {
    const int t = threadIdx.x;
    const int tco = t & 15, rq = (t >> 4) & 7, pu = t >> 7;
    const int b = blockIdx.z, co0 = blockIdx.y << 6;
    const int ty = blockIdx.x / 5, tx = blockIdx.x % 5;
    const int u0 = ty << 4, v0 = tx << 4;
    const int u = u0 + 2 * rq + pu;
    const int a0 = (u0 >> 1) - 1, c0 = (v0 >> 1) - 1;
    const int kend = (66 - v0) >> 1;   // valid even-v pairs (>=8 except v0=64 -> 1)

    __shared__ __align__(16) float sx[8][81];      // [ci][r*9+cc]
    __shared__ __align__(16) float sw[72][64];     // [(ci*9+k)][co]

    ull acc[16][2];
#pragma unroll
    for (int i = 0; i < 16; i++) { acc[i][0] = 0ULL; acc[i][1] = 0ULL; }

    for (int ci0 = 0; ci0 < 512; ci0 += 8) {
        __syncthreads();
#pragma unroll
        for (int m = 0; m < 3; m++) {
            int e = t + (m << 8);
            if (e < 648) {
                int ci = e / 81, rem = e - ci * 81;
                int r = rem / 9, cc = rem - r * 9;
                int a = a0 + r, c = c0 + cc;
                float v = 0.f;
                if ((unsigned)a < 32u && (unsigned)c < 32u)
                    v = g_xs[((size_t)(b * 512 + ci0 + ci) << 10) + (a << 5) + c];
                sx[ci][rem] = v;
            }
        }
#pragma unroll
        for (int m = 0; m < 5; m++) {
            int e = t + (m << 8);
            if (e < 1152) {
                int row = e >> 4, cq = e & 15;
                *(float4*)&sw[row][cq << 2] =
                    *(const float4*)&g_wt[(size_t)(ci0 * 9 + row) * 512 + co0 + (cq << 2)];
            }
        }
        __syncthreads();

        if (u < 65) {
#pragma unroll
            for (int ci = 0; ci < 8; ci++) {
                ull wv[9][2];
#pragma unroll
                for (int k = 0; k < 9; k++) {
                    ulonglong2 w2 = *(const ulonglong2*)&sw[ci * 9 + k][tco << 2];
                    wv[k][0] = w2.x; wv[k][1] = w2.y;
                }
                const float* xr1 = &sx[ci][(rq + 1) * 9];
                const float* xr2 = &sx[ci][rq * 9];
                if (pu == 0) {
#pragma unroll
                    for (int k = 0; k < 8; k++) {
                        if (v0 + 2 * k < 65) {
                            int cc = k + 1;
                            ull xA = pk2(xr1[cc]), xB = pk2(xr1[cc - 1]);
                            ull xC = pk2(xr2[cc]), xD = pk2(xr2[cc - 1]);
#pragma unroll
                            for (int h = 0; h < 2; h++) {
                                fma2(acc[2 * k][h], xA, wv[0][h]);
                                fma2(acc[2 * k][h], xB, wv[2][h]);
                                fma2(acc[2 * k][h], xC, wv[6][h]);
                                fma2(acc[2 * k][h], xD, wv[8][h]);
                                fma2(acc[2 * k + 1][h], xA, wv[1][h]);
                                fma2(acc[2 * k + 1][h], xC, wv[7][h]);
                            }
                        }
                    }
                } else {
#pragma unroll
                    for (int k = 0; k < 8; k++) {
                        if (v0 + 2 * k < 65) {
                            int cc = k + 1;
                            ull xA = pk2(xr1[cc]), xB = pk2(xr1[cc - 1]);
#pragma unroll
                            for (int h = 0; h < 2; h++) {
                                fma2(acc[2 * k][h], xA, wv[3][h]);
                                fma2(acc[2 * k][h], xB, wv[5][h]);
                                fma2(acc[2 * k + 1][h], xA, wv[4][h]);
                            }
                        }
                    }
                }
            }
        }
        (void)kend;
    }

    if (u < 65) {
        float4 dv = *(const float4*)&g_dcoef[b * 512 + co0 + (tco << 2)];
        size_t rowb = (size_t)(b * 65 + u) * 65;
#pragma unroll
        for (int k = 0; k < 8; k++) {
#pragma unroll
            for (int o = 0; o < 2; o++) {
                int v = v0 + 2 * k + o;
                if (v < 65) {
                    float2 L = up2(acc[2 * k + o][0]), H = up2(acc[2 * k + o][1]);
                    float4 r = make_float4(L.x * dv.x, L.y * dv.y, H.x * dv.z, H.y * dv.w);
                    *(float4*)(g_y1 + (rowb + v) * 512 + co0 + (tco << 2)) = r;
                }
            }
        }
    }
}

// ---------- K6: FIR (0.25,0.75,0.75,0.25)^2 + noise + bias + lrelu*sqrt2 + clamp ----------
__global__ void __launch_bounds__(256) k_fir(const float* __restrict__ noise,
                                             const float* __restrict__ nsp,
                                             const float* __restrict__ bias,
                                             float* __restrict__ out) {
    const int t = threadIdx.x, cg = t & 15, qi = t >> 4;
    const int b = blockIdx.z, co0 = blockIdx.y << 6, q0 = blockIdx.x << 4;
    const int q = q0 + qi, co = co0 + (cg << 2);
    __shared__ float st[16][65];

    const float ns = nsp[0];
    const float4 bi = *(const float4*)&bias[co];
    const float* yb = g_y1 + (size_t)b * 65 * 65 * 512 + co;

    auto hrow = [&](int r) -> float4 {
        float4 h = make_float4(0.f, 0.f, 0.f, 0.f);
        if ((unsigned)r < 65u) {
            const float* rp = yb + (size_t)r * 65 * 512;
#pragma unroll
            for (int j = 0; j < 4; j++) {
                int v = q - 1 + j;
                float g = (j == 0 || j == 3) ? 0.25f : 0.75f;
                if ((unsigned)v < 65u) {
                    float4 y = *(const float4*)(rp + (size_t)v * 512);
                    h.x += g * y.x; h.y += g * y.y; h.z += g * y.z; h.w += g * y.w;
                }
            }
        }
        return h;
    };

    float4 h0 = make_float4(0.f, 0.f, 0.f, 0.f);
    float4 h1 = hrow(0), h2 = hrow(1), h3;

    for (int p = 0; p < 64; p++) {
        h3 = hrow(p + 2);
        float4 o;
        o.x = 0.25f * (h0.x + h3.x) + 0.75f * (h1.x + h2.x);
        o.y = 0.25f * (h0.y + h3.y) + 0.75f * (h1.y + h2.y);
        o.z = 0.25f * (h0.z + h3.z) + 0.75f * (h1.z + h2.z);
        o.w = 0.25f * (h0.w + h3.w) + 0.75f * (h1.w + h2.w);

        float nz = noise[((b << 6) + p) * 64 + q] * ns;
        float vv[4] = {o.x + nz + bi.x, o.y + nz + bi.y, o.z + nz + bi.z, o.w + nz + bi.w};
#pragma unroll
        for (int i = 0; i < 4; i++) {
            float v = vv[i];
            v = (v > 0.f ? v : 0.2f * v) * 1.4142135623730951f;
            v = fminf(fmaxf(v, -256.f), 256.f);
            st[qi][(cg << 2) + i] = v;
        }
        __syncthreads();
        {
            int cop = t >> 2, qp = (t & 3) << 2;
            float4 w4 = make_float4(st[qp][cop], st[qp + 1][cop], st[qp + 2][cop], st[qp + 3][cop]);
            *(float4*)&out[(((size_t)b * 512 + co0 + cop) * 64 + p) * 64 + q0 + qp] = w4;
        }
        __syncthreads();
        h0 = h1; h1 = h2; h2 = h3;
    }
}

// ---------- launch ----------
extern "C" void kernel_launch(void* const* d_in, const int* in_sizes, int n_in,
                              void* d_out, int out_size) {
    const float* x  = (const float*)d_in[0];
    const float* wl = (const float*)d_in[1];
    const float* aw = (const float*)d_in[2];
    const float* ab = (const float*)d_in[3];
    const float* cw = (const float*)d_in[4];
    const float* nz = (const float*)d_in[5];
    const float* ns = (const float*)d_in[6];
    const float* bi = (const float*)d_in[7];
    float* out = (float*)d_out;

    k_style<<<dim3(2, 16), 256>>>(wl, aw, ab);
    k_prep<<<512, 512>>>(cw);
    k_modx<<<8192, 256>>>(x);
    k_dcoef<<<dim3(2, 16), 256>>>();
    k_conv<<<dim3(25, 8, 16), 256>>>();
    k_fir<<<dim3(4, 8, 16), 256>>>(nz, ns, bi, out);
}

// round 13
// speedup vs baseline: 1.9386x; 1.9386x over previous
#include <cuda_runtime.h>
#include <stdint.h>

typedef unsigned long long ull;

// ---------- static device scratch ----------
__device__ __align__(128) float g_style[16 * 512];
__device__ __align__(128) float g_dcoef[16 * 512];
__device__ __align__(128) float g_wsqT[512 * 512];
__device__ __align__(128) float g_wt[512 * 9 * 512];                 // [(ci*9+k)][co]
__device__ __align__(128) float g_xs[16 * 512 * 1024];               // x * style
__device__ __align__(128) float g_y1[(size_t)16 * 65 * 65 * 512];    // [b][u][v][co]

__device__ __forceinline__ ull pk2(float v) {
    ull r; asm("mov.b64 %0,{%1,%2};" : "=l"(r) : "f"(v), "f"(v)); return r;
}
__device__ __forceinline__ void fma2(ull& d, ull a, ull b) {
    asm("fma.rn.f32x2 %0,%1,%2,%0;" : "+l"(d) : "l"(a), "l"(b));
}
__device__ __forceinline__ float2 up2(ull v) {
    float2 r; asm("mov.b64 {%0,%1},%2;" : "=f"(r.x), "=f"(r.y) : "l"(v)); return r;
}
__device__ __forceinline__ uint32_t sma(const void* p) {
    return (uint32_t)__cvta_generic_to_shared(p);
}
__device__ __forceinline__ void cpa4(uint32_t d, const float* s, bool ok) {
    int sz = ok ? 4 : 0;
    asm volatile("cp.async.ca.shared.global [%0],[%1],4,%2;" :: "r"(d), "l"(s), "r"(sz));
}
__device__ __forceinline__ void cpa16(uint32_t d, const float* s) {
    asm volatile("cp.async.cg.shared.global [%0],[%1],16;" :: "r"(d), "l"(s));
}
__device__ __forceinline__ void cpcommit() { asm volatile("cp.async.commit_group;"); }
template <int N> __device__ __forceinline__ void cpwait() {
    asm volatile("cp.async.wait_group %0;" :: "n"(N));
}

// ---------- K1: style[b][ci] ----------
__global__ void k_style(const float* __restrict__ wl, const float* __restrict__ aw,
                        const float* __restrict__ ab) {
    __shared__ float s[512];
    int b = blockIdx.y, ci = blockIdx.x * 256 + threadIdx.x;
    for (int i = threadIdx.x; i < 512; i += 256) s[i] = wl[b * 512 + i];
    __syncthreads();
    const float* a = aw + (size_t)ci * 512;
    float acc = 0.f;
#pragma unroll 8
    for (int d = 0; d < 512; d++) acc += s[d] * a[d];
    g_style[b * 512 + ci] = acc * 0.04419417382415922f + ab[ci];
}

// ---------- K2: weight transpose + sum of squares ----------
__global__ void k_prep(const float* __restrict__ cw) {
    int ci = blockIdx.x, co = threadIdx.x;
    const float* p = cw + ((size_t)co * 512 + ci) * 9;
    float s = 0.f;
#pragma unroll
    for (int k = 0; k < 9; k++) {
        float v = p[k];
        g_wt[(size_t)(ci * 9 + k) * 512 + co] = v;
        s += v * v;
    }
    g_wsqT[ci * 512 + co] = s;
}

// ---------- K3: xs = x * style ----------
__global__ void k_modx(const float* __restrict__ x) {
    int i = blockIdx.x * 256 + threadIdx.x;
    float4 v = ((const float4*)x)[i];
    float s = g_style[i >> 8];
    v.x *= s; v.y *= s; v.z *= s; v.w *= s;
    ((float4*)g_xs)[i] = v;
}

// ---------- K4: dcoef[b][co] ----------
__global__ void k_dcoef() {
    __shared__ float s2[2048];   // [ci][4 b-local]
    int t = threadIdx.x;
    int co = blockIdx.x * 256 + t, b0 = blockIdx.y * 4;
    for (int i = t; i < 2048; i += 256) {
        int ci = i >> 2, bl = i & 3;
        float v = g_style[(b0 + bl) * 512 + ci];
        s2[i] = v * v;
    }
    __syncthreads();
    float a0 = 0.f, a1 = 0.f, a2 = 0.f, a3 = 0.f;
#pragma unroll 4
    for (int ci = 0; ci < 512; ci++) {
        float w = g_wsqT[ci * 512 + co];
        float4 s = *(const float4*)&s2[ci << 2];
        a0 += w * s.x; a1 += w * s.y; a2 += w * s.z; a3 += w * s.w;
    }
    g_dcoef[(b0 + 0) * 512 + co] = rsqrtf(a0 + 1e-8f);
    g_dcoef[(b0 + 1) * 512 + co] = rsqrtf(a1 + 1e-8f);
    g_dcoef[(b0 + 2) * 512 + co] = rsqrtf(a2 + 1e-8f);
    g_dcoef[(b0 + 3) * 512 + co] = rsqrtf(a3 + 1e-8f);
}

// ---------- K5: interior transposed conv (u,v in [0,64)), double-buffered ----------
__global__ void __launch_bounds__(256, 1) k_conv() {
    const int t = threadIdx.x;
    const int tco = t & 15, rq = (t >> 4) & 7, pu = t >> 7;
    const int b = blockIdx.z, co0 = blockIdx.y << 6;
    const int ty = blockIdx.x >> 2, tx = blockIdx.x & 3;
    const int u = (ty << 4) + 2 * rq + pu;
    const int a0 = (ty << 3) - 1, c0 = (tx << 3) - 1;

    __shared__ __align__(16) float s_x[2][648];    // [ci8][r9*9+cc9]
    __shared__ __align__(16) float s_w[2][4608];   // [(ci*9+k)][64 co]

    // load slots
    const float* xp[3]; bool xv[3];
#pragma unroll
    for (int m = 0; m < 3; m++) {
        int e = t + (m << 8);
        if (e < 648) {
            int ci = e / 81, rem = e - ci * 81;
            int r = rem / 9, cc = rem - r * 9;
            int a = a0 + r, c = c0 + cc;
            bool ok = ((unsigned)a < 32u) && ((unsigned)c < 32u);
            xv[m] = ok;
            xp[m] = g_xs + ((size_t)(b * 512 + ci) << 10) + (ok ? (a << 5) + c : 0);
        } else { xv[m] = false; xp[m] = g_xs; }
    }
    const float* wp[5];
#pragma unroll
    for (int m = 0; m < 5; m++) {
        int f = t + (m << 8);
        wp[m] = (f < 1152) ? (g_wt + (size_t)(f >> 4) * 512 + co0 + ((f & 15) << 2)) : g_wt;
    }
    uint32_t sxa[2] = { sma(s_x[0]), sma(s_x[1]) };
    uint32_t swa[2] = { sma(s_w[0]), sma(s_w[1]) };

    ull acc[16][2];
#pragma unroll
    for (int i = 0; i < 16; i++) { acc[i][0] = 0ULL; acc[i][1] = 0ULL; }

    auto issue = [&](int nb) {
#pragma unroll
        for (int m = 0; m < 3; m++) {
            int e = t + (m << 8);
            if (e < 648) { cpa4(sxa[nb] + (e << 2), xp[m], xv[m]); xp[m] += 8192; }
        }
#pragma unroll
        for (int m = 0; m < 5; m++) {
            int f = t + (m << 8);
            if (f < 1152) { cpa16(swa[nb] + (f << 4), wp[m]); wp[m] += 36864; }
        }
        cpcommit();
    };

    issue(0);

    for (int c = 0; c < 64; c++) {
        if (c < 63) { issue((c + 1) & 1); cpwait<1>(); }
        else cpwait<0>();
        __syncthreads();

        const float* sx = s_x[c & 1];
        const float* sw = s_w[c & 1];
#pragma unroll
        for (int ci = 0; ci < 8; ci++) {
            ull wv[9][2];
#pragma unroll
            for (int k = 0; k < 9; k++) {
                ulonglong2 w2 = *(const ulonglong2*)&sw[(ci * 9 + k) * 64 + (tco << 2)];
                wv[k][0] = w2.x; wv[k][1] = w2.y;
            }
            const float* x1 = &sx[ci * 81 + (rq + 1) * 9];
            ull p1[9];
#pragma unroll
            for (int j = 0; j < 9; j++) p1[j] = pk2(x1[j]);
            if (pu == 0) {
                const float* x2 = &sx[ci * 81 + rq * 9];
                ull p2[9];
#pragma unroll
                for (int j = 0; j < 9; j++) p2[j] = pk2(x2[j]);
#pragma unroll
                for (int k = 0; k < 8; k++) {
#pragma unroll
                    for (int h = 0; h < 2; h++) {
                        fma2(acc[2 * k][h], p1[k + 1], wv[0][h]);
                        fma2(acc[2 * k][h], p1[k],     wv[2][h]);
                        fma2(acc[2 * k][h], p2[k + 1], wv[6][h]);
                        fma2(acc[2 * k][h], p2[k],     wv[8][h]);
                        fma2(acc[2 * k + 1][h], p1[k + 1], wv[1][h]);
                        fma2(acc[2 * k + 1][h], p2[k + 1], wv[7][h]);
                    }
                }
            } else {
#pragma unroll
                for (int k = 0; k < 8; k++) {
#pragma unroll
                    for (int h = 0; h < 2; h++) {
                        fma2(acc[2 * k][h], p1[k + 1], wv[3][h]);
                        fma2(acc[2 * k][h], p1[k],     wv[5][h]);
                        fma2(acc[2 * k + 1][h], p1[k + 1], wv[4][h]);
                    }
                }
            }
        }
        __syncthreads();
    }

    float4 dv = *(const float4*)&g_dcoef[b * 512 + co0 + (tco << 2)];
    size_t rowb = (size_t)(b * 65 + u) * 65;
#pragma unroll
    for (int k = 0; k < 8; k++) {
#pragma unroll
        for (int o = 0; o < 2; o++) {
            int v = (tx << 4) + 2 * k + o;
            float2 L = up2(acc[2 * k + o][0]), H = up2(acc[2 * k + o][1]);
            float4 r = make_float4(L.x * dv.x, L.y * dv.y, H.x * dv.z, H.y * dv.w);
            *(float4*)(g_y1 + (rowb + v) * 512 + co0 + (tco << 2)) = r;
        }
    }
}

// ---------- K5b: edges. mode0: u=64 row (v in [0,65)); mode1: v=64 col (u in [0,64)) ----------
// y[64,2C]=xs[31,C]k6+xs[31,C-1]k8 ; y[64,2C+1]=xs[31,C]k7
// y[2A,64]=xs[A,31]k2+xs[A-1,31]k8 ; y[2A+1,64]=xs[A,31]k5
__global__ void __launch_bounds__(256) k_edge() {
    const int t = threadIdx.x, c = t & 127, half = t >> 7;
    const int cb = blockIdx.x, co = cb * 128 + c, b = blockIdx.y, mode = blockIdx.z;
    const int base = half * 33;
    const int np = half ? (mode ? 31 : 32) : 33;
    const int ka = mode ? 2 : 6, kb = mode ? 5 : 7;

    __shared__ float sw[16][3][128];
    __shared__ float sx[16][34];   // slot s = value at index s-1; OOB -> 0

    float acc[33];
#pragma unroll
    for (int i = 0; i < 33; i++) acc[i] = 0.f;

    for (int ci0 = 0; ci0 < 512; ci0 += 16) {
        __syncthreads();
#pragma unroll
        for (int m = 0; m < 24; m++) {
            int e = t + (m << 8);
            int ci = e / 384, rem = e - ci * 384;
            int k3 = rem >> 7, cc = rem & 127;
            int kidx = (k3 == 0) ? ka : ((k3 == 1) ? kb : 8);
            sw[ci][k3][cc] = g_wt[(size_t)((ci0 + ci) * 9 + kidx) * 512 + cb * 128 + cc];
        }
#pragma unroll
        for (int m = 0; m < 3; m++) {
            int e = t + (m << 8);
            if (e < 544) {
                int ci = e / 34, s = e - ci * 34, j = s - 1;
                float v = 0.f;
                if ((unsigned)j < 32u)
                    v = g_xs[((size_t)(b * 512 + ci0 + ci) << 10) +
                             (mode ? (j << 5) + 31 : (31 << 5) + j)];
                sx[ci][s] = v;
            }
        }
        __syncthreads();
#pragma unroll 4
        for (int ci = 0; ci < 16; ci++) {
            float wa = sw[ci][0][c], wb = sw[ci][1][c], wc = sw[ci][2][c];
#pragma unroll
            for (int i = 0; i < 33; i++) {
                if (i < np) {
                    int o = base + i, C = o >> 1;
                    if (o & 1) acc[i] += sx[ci][C + 1] * wb;
                    else       acc[i] += sx[ci][C + 1] * wa + sx[ci][C] * wc;
                }
            }
        }
    }

    float d = g_dcoef[b * 512 + co];
#pragma unroll
    for (int i = 0; i < 33; i++) {
        if (i < np) {
            int o = base + i;
            size_t off = mode ? ((size_t)(b * 65 + o) * 65 + 64) * 512 + co
                              : ((size_t)(b * 65 + 64) * 65 + o) * 512 + co;
            g_y1[off] = acc[i] * d;
        }
    }
}

// ---------- K6: FIR + noise + bias + lrelu*sqrt2 + clamp ----------
__global__ void __launch_bounds__(256) k_fir(const float* __restrict__ noise,
                                             const float* __restrict__ nsp,
                                             const float* __restrict__ bias,
                                             float* __restrict__ out) {
    const int t = threadIdx.x, cg = t & 15, qi = t >> 4;
    const int b = blockIdx.z, co0 = blockIdx.y << 6, q0 = blockIdx.x << 4;
    const int q = q0 + qi, co = co0 + (cg << 2);
    __shared__ float st[16][65];

    const float ns = nsp[0];
    const float4 bi = *(const float4*)&bias[co];
    const float* yb = g_y1 + (size_t)b * 65 * 65 * 512 + co;

    auto hrow = [&](int r) -> float4 {
        float4 h = make_float4(0.f, 0.f, 0.f, 0.f);
        if ((unsigned)r < 65u) {
            const float* rp = yb + (size_t)r * 65 * 512;
#pragma unroll
            for (int j = 0; j < 4; j++) {
                int v = q - 1 + j;
                float g = (j == 0 || j == 3) ? 0.25f : 0.75f;
                if ((unsigned)v < 65u) {
                    float4 y = *(const float4*)(rp + (size_t)v * 512);
                    h.x += g * y.x; h.y += g * y.y; h.z += g * y.z; h.w += g * y.w;
                }
            }
        }
        return h;
    };

    float4 h0 = make_float4(0.f, 0.f, 0.f, 0.f);
    float4 h1 = hrow(0), h2 = hrow(1), h3;

    for (int p = 0; p < 64; p++) {
        h3 = hrow(p + 2);
        float4 o;
        o.x = 0.25f * (h0.x + h3.x) + 0.75f * (h1.x + h2.x);
        o.y = 0.25f * (h0.y + h3.y) + 0.75f * (h1.y + h2.y);
        o.z = 0.25f * (h0.z + h3.z) + 0.75f * (h1.z + h2.z);
        o.w = 0.25f * (h0.w + h3.w) + 0.75f * (h1.w + h2.w);

        float nz = noise[((b << 6) + p) * 64 + q] * ns;
        float vv[4] = {o.x + nz + bi.x, o.y + nz + bi.y, o.z + nz + bi.z, o.w + nz + bi.w};
#pragma unroll
        for (int i = 0; i < 4; i++) {
            float v = vv[i];
            v = (v > 0.f ? v : 0.2f * v) * 1.4142135623730951f;
            v = fminf(fmaxf(v, -256.f), 256.f);
            st[qi][(cg << 2) + i] = v;
        }
        __syncthreads();
        {
            int cop = t >> 2, qp = (t & 3) << 2;
            float4 w4 = make_float4(st[qp][cop], st[qp + 1][cop], st[qp + 2][cop], st[qp + 3][cop]);
            *(float4*)&out[(((size_t)b * 512 + co0 + cop) * 64 + p) * 64 + q0 + qp] = w4;
        }
        __syncthreads();
        h0 = h1; h1 = h2; h2 = h3;
    }
}

// ---------- launch ----------
extern "C" void kernel_launch(void* const* d_in, const int* in_sizes, int n_in,
                              void* d_out, int out_size) {
    const float* x  = (const float*)d_in[0];
    const float* wl = (const float*)d_in[1];
    const float* aw = (const float*)d_in[2];
    const float* ab = (const float*)d_in[3];
    const float* cw = (const float*)d_in[4];
    const float* nz = (const float*)d_in[5];
    const float* ns = (const float*)d_in[6];
    const float* bi = (const float*)d_in[7];
    float* out = (float*)d_out;

    k_style<<<dim3(2, 16), 256>>>(wl, aw, ab);
    k_prep<<<512, 512>>>(cw);
    k_modx<<<8192, 256>>>(x);
    k_dcoef<<<dim3(2, 4), 256>>>();
    k_conv<<<dim3(16, 8, 16), 256>>>();
    k_edge<<<dim3(4, 16, 2), 256>>>();
    k_fir<<<dim3(4, 8, 16), 256>>>(nz, ns, bi, out);
}

// round 17
// speedup vs baseline: 1.9388x; 1.0001x over previous
#include <cuda_runtime.h>
#include <stdint.h>

typedef unsigned long long ull;

// ---------- static device scratch ----------
__device__ __align__(128) float g_style[16 * 512];
__device__ __align__(128) float g_dcoef[16 * 512];
__device__ __align__(128) float g_wsqT[512 * 512];
__device__ __align__(128) float g_wt[512 * 9 * 512];                 // [(ci*9+k)][co]
__device__ __align__(128) float g_xs[16 * 512 * 1024];               // x * style
__device__ __align__(128) float g_y1[(size_t)16 * 65 * 65 * 512];    // [b][u][v][co]

__device__ __forceinline__ ull pk2(float v) {
    ull r; asm("mov.b64 %0,{%1,%2};" : "=l"(r) : "f"(v), "f"(v)); return r;
}
__device__ __forceinline__ void fma2(ull& d, ull a, ull b) {
    asm("fma.rn.f32x2 %0,%1,%2,%0;" : "+l"(d) : "l"(a), "l"(b));
}
__device__ __forceinline__ float2 up2(ull v) {
    float2 r; asm("mov.b64 {%0,%1},%2;" : "=f"(r.x), "=f"(r.y) : "l"(v)); return r;
}
__device__ __forceinline__ uint32_t sma(const void* p) {
    return (uint32_t)__cvta_generic_to_shared(p);
}
__device__ __forceinline__ void cpa4(uint32_t d, const float* s, bool ok) {
    int sz = ok ? 4 : 0;
    asm volatile("cp.async.ca.shared.global [%0],[%1],4,%2;" :: "r"(d), "l"(s), "r"(sz));
}
__device__ __forceinline__ void cpa16(uint32_t d, const float* s) {
    asm volatile("cp.async.cg.shared.global [%0],[%1],16;" :: "r"(d), "l"(s));
}
__device__ __forceinline__ void cpcommit() { asm volatile("cp.async.commit_group;"); }
template <int N> __device__ __forceinline__ void cpwait() {
    asm volatile("cp.async.wait_group %0;" :: "n"(N));
}

// ---------- K1: style[b][ci] ----------
__global__ void k_style(const float* __restrict__ wl, const float* __restrict__ aw,
                        const float* __restrict__ ab) {
    __shared__ float s[512];
    int b = blockIdx.y, ci = blockIdx.x * 256 + threadIdx.x;
    for (int i = threadIdx.x; i < 512; i += 256) s[i] = wl[b * 512 + i];
    __syncthreads();
    const float* a = aw + (size_t)ci * 512;
    float acc = 0.f;
#pragma unroll 8
    for (int d = 0; d < 512; d++) acc += s[d] * a[d];
    g_style[b * 512 + ci] = acc * 0.04419417382415922f + ab[ci];
}

// ---------- K2: weight transpose + sum of squares ----------
__global__ void k_prep(const float* __restrict__ cw) {
    int ci = blockIdx.x, co = threadIdx.x;
    const float* p = cw + ((size_t)co * 512 + ci) * 9;
    float s = 0.f;
#pragma unroll
    for (int k = 0; k < 9; k++) {
        float v = p[k];
        g_wt[(size_t)(ci * 9 + k) * 512 + co] = v;
        s += v * v;
    }
    g_wsqT[ci * 512 + co] = s;
}

// ---------- K3: xs = x * style ----------
__global__ void k_modx(const float* __restrict__ x) {
    int i = blockIdx.x * 256 + threadIdx.x;
    float4 v = ((const float4*)x)[i];
    float s = g_style[i >> 8];
    v.x *= s; v.y *= s; v.z *= s; v.w *= s;
    ((float4*)g_xs)[i] = v;
}

// ---------- K4: dcoef[b][co] ----------
__global__ void k_dcoef() {
    __shared__ float s2[2048];   // [ci][4 b-local]
    int t = threadIdx.x;
    int co = blockIdx.x * 256 + t, b0 = blockIdx.y * 4;
    for (int i = t; i < 2048; i += 256) {
        int ci = i >> 2, bl = i & 3;
        float v = g_style[(b0 + bl) * 512 + ci];
        s2[i] = v * v;
    }
    __syncthreads();
    float a0 = 0.f, a1 = 0.f, a2 = 0.f, a3 = 0.f;
#pragma unroll 4
    for (int ci = 0; ci < 512; ci++) {
        float w = g_wsqT[ci * 512 + co];
        float4 s = *(const float4*)&s2[ci << 2];
        a0 += w * s.x; a1 += w * s.y; a2 += w * s.z; a3 += w * s.w;
    }
    g_dcoef[(b0 + 0) * 512 + co] = rsqrtf(a0 + 1e-8f);
    g_dcoef[(b0 + 1) * 512 + co] = rsqrtf(a1 + 1e-8f);
    g_dcoef[(b0 + 2) * 512 + co] = rsqrtf(a2 + 1e-8f);
    g_dcoef[(b0 + 3) * 512 + co] = rsqrtf(a3 + 1e-8f);
}

// ---------- K5: interior transposed conv (u,v in [0,64)), double-buffered ----------
__global__ void __launch_bounds__(256, 1) k_conv() {
    const int t = threadIdx.x;
    const int tco = t & 15, rq = (t >> 4) & 7, pu = t >> 7;
    const int b = blockIdx.z, co0 = blockIdx.y << 6;
    const int ty = blockIdx.x >> 2, tx = blockIdx.x & 3;
    const int u = (ty << 4) + 2 * rq + pu;
    const int a0 = (ty << 3) - 1, c0 = (tx << 3) - 1;

    __shared__ __align__(16) float s_x[2][648];    // [ci8][r9*9+cc9]
    __shared__ __align__(16) float s_w[2][4608];   // [(ci*9+k)][64 co]

    // load slots
    const float* xp[3]; bool xv[3];
#pragma unroll
    for (int m = 0; m < 3; m++) {
        int e = t + (m << 8);
        if (e < 648) {
            int ci = e / 81, rem = e - ci * 81;
            int r = rem / 9, cc = rem - r * 9;
            int a = a0 + r, c = c0 + cc;
            bool ok = ((unsigned)a < 32u) && ((unsigned)c < 32u);
            xv[m] = ok;
            xp[m] = g_xs + ((size_t)(b * 512 + ci) << 10) + (ok ? (a << 5) + c : 0);
        } else { xv[m] = false; xp[m] = g_xs; }
    }
    const float* wp[5];
#pragma unroll
    for (int m = 0; m < 5; m++) {
        int f = t + (m << 8);
        wp[m] = (f < 1152) ? (g_wt + (size_t)(f >> 4) * 512 + co0 + ((f & 15) << 2)) : g_wt;
    }
    uint32_t sxa[2] = { sma(s_x[0]), sma(s_x[1]) };
    uint32_t swa[2] = { sma(s_w[0]), sma(s_w[1]) };

    ull acc[16][2];
#pragma unroll
    for (int i = 0; i < 16; i++) { acc[i][0] = 0ULL; acc[i][1] = 0ULL; }

    auto issue = [&](int nb) {
#pragma unroll
        for (int m = 0; m < 3; m++) {
            int e = t + (m << 8);
            if (e < 648) { cpa4(sxa[nb] + (e << 2), xp[m], xv[m]); xp[m] += 8192; }
        }
#pragma unroll
        for (int m = 0; m < 5; m++) {
            int f = t + (m << 8);
            if (f < 1152) { cpa16(swa[nb] + (f << 4), wp[m]); wp[m] += 36864; }
        }
        cpcommit();
    };

    issue(0);

    for (int c = 0; c < 64; c++) {
        if (c < 63) { issue((c + 1) & 1); cpwait<1>(); }
        else cpwait<0>();
        __syncthreads();

        const float* sx = s_x[c & 1];
        const float* sw = s_w[c & 1];
#pragma unroll
        for (int ci = 0; ci < 8; ci++) {
            ull wv[9][2];
#pragma unroll
            for (int k = 0; k < 9; k++) {
                ulonglong2 w2 = *(const ulonglong2*)&sw[(ci * 9 + k) * 64 + (tco << 2)];
                wv[k][0] = w2.x; wv[k][1] = w2.y;
            }
            const float* x1 = &sx[ci * 81 + (rq + 1) * 9];
            ull p1[9];
#pragma unroll
            for (int j = 0; j < 9; j++) p1[j] = pk2(x1[j]);
            if (pu == 0) {
                const float* x2 = &sx[ci * 81 + rq * 9];
                ull p2[9];
#pragma unroll
                for (int j = 0; j < 9; j++) p2[j] = pk2(x2[j]);
#pragma unroll
                for (int k = 0; k < 8; k++) {
#pragma unroll
                    for (int h = 0; h < 2; h++) {
                        fma2(acc[2 * k][h], p1[k + 1], wv[0][h]);
                        fma2(acc[2 * k][h], p1[k],     wv[2][h]);
                        fma2(acc[2 * k][h], p2[k + 1], wv[6][h]);
                        fma2(acc[2 * k][h], p2[k],     wv[8][h]);
                        fma2(acc[2 * k + 1][h], p1[k + 1], wv[1][h]);
                        fma2(acc[2 * k + 1][h], p2[k + 1], wv[7][h]);
                    }
                }
            } else {
#pragma unroll
                for (int k = 0; k < 8; k++) {
#pragma unroll
                    for (int h = 0; h < 2; h++) {
                        fma2(acc[2 * k][h], p1[k + 1], wv[3][h]);
                        fma2(acc[2 * k][h], p1[k],     wv[5][h]);
                        fma2(acc[2 * k + 1][h], p1[k + 1], wv[4][h]);
                    }
                }
            }
        }
        __syncthreads();
    }

    float4 dv = *(const float4*)&g_dcoef[b * 512 + co0 + (tco << 2)];
    size_t rowb = (size_t)(b * 65 + u) * 65;
#pragma unroll
    for (int k = 0; k < 8; k++) {
#pragma unroll
        for (int o = 0; o < 2; o++) {
            int v = (tx << 4) + 2 * k + o;
            float2 L = up2(acc[2 * k + o][0]), H = up2(acc[2 * k + o][1]);
            float4 r = make_float4(L.x * dv.x, L.y * dv.y, H.x * dv.z, H.y * dv.w);
            *(float4*)(g_y1 + (rowb + v) * 512 + co0 + (tco << 2)) = r;
        }
    }
}

// ---------- K5b: edges. mode0: u=64 row (v in [0,65)); mode1: v=64 col (u in [0,64)) ----------
// y[64,2C]=xs[31,C]k6+xs[31,C-1]k8 ; y[64,2C+1]=xs[31,C]k7
// y[2A,64]=xs[A,31]k2+xs[A-1,31]k8 ; y[2A+1,64]=xs[A,31]k5
__global__ void __launch_bounds__(256) k_edge() {
    const int t = threadIdx.x, c = t & 127, half = t >> 7;
    const int cb = blockIdx.x, co = cb * 128 + c, b = blockIdx.y, mode = blockIdx.z;
    const int base = half * 33;
    const int np = half ? (mode ? 31 : 32) : 33;
    const int ka = mode ? 2 : 6, kb = mode ? 5 : 7;

    __shared__ float sw[16][3][128];
    __shared__ float sx[16][34];   // slot s = value at index s-1; OOB -> 0

    float acc[33];
#pragma unroll
    for (int i = 0; i < 33; i++) acc[i] = 0.f;

    for (int ci0 = 0; ci0 < 512; ci0 += 16) {
        __syncthreads();
#pragma unroll
        for (int m = 0; m < 24; m++) {
            int e = t + (m << 8);
            int ci = e / 384, rem = e - ci * 384;
            int k3 = rem >> 7, cc = rem & 127;
            int kidx = (k3 == 0) ? ka : ((k3 == 1) ? kb : 8);
            sw[ci][k3][cc] = g_wt[(size_t)((ci0 + ci) * 9 + kidx) * 512 + cb * 128 + cc];
        }
#pragma unroll
        for (int m = 0; m < 3; m++) {
            int e = t + (m << 8);
            if (e < 544) {
                int ci = e / 34, s = e - ci * 34, j = s - 1;
                float v = 0.f;
                if ((unsigned)j < 32u)
                    v = g_xs[((size_t)(b * 512 + ci0 + ci) << 10) +
                             (mode ? (j << 5) + 31 : (31 << 5) + j)];
                sx[ci][s] = v;
            }
        }
        __syncthreads();
#pragma unroll 4
        for (int ci = 0; ci < 16; ci++) {
            float wa = sw[ci][0][c], wb = sw[ci][1][c], wc = sw[ci][2][c];
#pragma unroll
            for (int i = 0; i < 33; i++) {
                if (i < np) {
                    int o = base + i, C = o >> 1;
                    if (o & 1) acc[i] += sx[ci][C + 1] * wb;
                    else       acc[i] += sx[ci][C + 1] * wa + sx[ci][C] * wc;
                }
            }
        }
    }

    float d = g_dcoef[b * 512 + co];
#pragma unroll
    for (int i = 0; i < 33; i++) {
        if (i < np) {
            int o = base + i;
            size_t off = mode ? ((size_t)(b * 65 + o) * 65 + 64) * 512 + co
                              : ((size_t)(b * 65 + 64) * 65 + o) * 512 + co;
            g_y1[off] = acc[i] * d;
        }
    }
}

// ---------- K6: FIR + noise + bias + lrelu*sqrt2 + clamp ----------
__global__ void __launch_bounds__(256) k_fir(const float* __restrict__ noise,
                                             const float* __restrict__ nsp,
                                             const float* __restrict__ bias,
                                             float* __restrict__ out) {
    const int t = threadIdx.x, cg = t & 15, qi = t >> 4;
    const int b = blockIdx.z, co0 = blockIdx.y << 6, q0 = blockIdx.x << 4;
    const int q = q0 + qi, co = co0 + (cg << 2);
    __shared__ float st[16][65];

    const float ns = nsp[0];
    const float4 bi = *(const float4*)&bias[co];
    const float* yb = g_y1 + (size_t)b * 65 * 65 * 512 + co;

    auto hrow = [&](int r) -> float4 {
        float4 h = make_float4(0.f, 0.f, 0.f, 0.f);
        if ((unsigned)r < 65u) {
            const float* rp = yb + (size_t)r * 65 * 512;
#pragma unroll
            for (int j = 0; j < 4; j++) {
                int v = q - 1 + j;
                float g = (j == 0 || j == 3) ? 0.25f : 0.75f;
                if ((unsigned)v < 65u) {
                    float4 y = *(const float4*)(rp + (size_t)v * 512);
                    h.x += g * y.x; h.y += g * y.y; h.z += g * y.z; h.w += g * y.w;
                }
            }
        }
        return h;
    };

    float4 h0 = make_float4(0.f, 0.f, 0.f, 0.f);
    float4 h1 = hrow(0), h2 = hrow(1), h3;

    for (int p = 0; p < 64; p++) {
        h3 = hrow(p + 2);
        float4 o;
        o.x = 0.25f * (h0.x + h3.x) + 0.75f * (h1.x + h2.x);
        o.y = 0.25f * (h0.y + h3.y) + 0.75f * (h1.y + h2.y);
        o.z = 0.25f * (h0.z + h3.z) + 0.75f * (h1.z + h2.z);
        o.w = 0.25f * (h0.w + h3.w) + 0.75f * (h1.w + h2.w);

        float nz = noise[((b << 6) + p) * 64 + q] * ns;
        float vv[4] = {o.x + nz + bi.x, o.y + nz + bi.y, o.z + nz + bi.z, o.w + nz + bi.w};
#pragma unroll
        for (int i = 0; i < 4; i++) {
            float v = vv[i];
            v = (v > 0.f ? v : 0.2f * v) * 1.4142135623730951f;
            v = fminf(fmaxf(v, -256.f), 256.f);
            st[qi][(cg << 2) + i] = v;
        }
        __syncthreads();
        {
            int cop = t >> 2, qp = (t & 3) << 2;
            float4 w4 = make_float4(st[qp][cop], st[qp + 1][cop], st[qp + 2][cop], st[qp + 3][cop]);
            *(float4*)&out[(((size_t)b * 512 + co0 + cop) * 64 + p) * 64 + q0 + qp] = w4;
        }
        __syncthreads();
        h0 = h1; h1 = h2; h2 = h3;
    }
}

// ---------- launch ----------
extern "C" void kernel_launch(void* const* d_in, const int* in_sizes, int n_in,
                              void* d_out, int out_size) {
    const float* x  = (const float*)d_in[0];
    const float* wl = (const float*)d_in[1];
    const float* aw = (const float*)d_in[2];
    const float* ab = (const float*)d_in[3];
    const float* cw = (const float*)d_in[4];
    const float* nz = (const float*)d_in[5];
    const float* ns = (const float*)d_in[6];
    const float* bi = (const float*)d_in[7];
    float* out = (float*)d_out;

    k_style<<<dim3(2, 16), 256>>>(wl, aw, ab);
    k_prep<<<512, 512>>>(cw);
    k_modx<<<8192, 256>>>(x);
    k_dcoef<<<dim3(2, 4), 256>>>();
    k_conv<<<dim3(16, 8, 16), 256>>>();
    k_edge<<<dim3(4, 16, 2), 256>>>();
    k_fir<<<dim3(4, 8, 16), 256>>>(nz, ns, bi, out);
}